// round 15
// baseline (speedup 1.0000x reference)
#include <cuda_runtime.h>
#include <cuda_fp16.h>
#include <mma.h>
#include <cstdint>

using namespace nvcuda;

#define NN 512
#define NTHREADS 256

// ---- device scratch ----
__device__ float g_A0[NN * 384];
__device__ __half g_B0h[NN * 384];                  // fp16 per-j trunk bias
__device__ float g_Af[NN * 128];
__device__ __align__(16) __half g_Bfh[NN * 128];    // fp16 per-j final bias (prefetched to SMEM)
__device__ __align__(16) __half g_Wmh[128 * 512];   // merged [w_t0 rows0:128 | w_fin rows0:128]
__device__ __align__(16) __half g_w1rh[384 * 384];  // w_t1 half
__device__ __align__(16) __half g_wfrh[384 * 128];  // w_fin half

__device__ __forceinline__ uint32_t smem_u32(const void* p) {
    uint32_t a;
    asm("{ .reg .u64 t; cvta.to.shared.u64 t, %1; cvt.u32.u64 %0, t; }" : "=r"(a) : "l"(p));
    return a;
}
__device__ __forceinline__ void cpa16(uint32_t s, const void* g) {
    asm volatile("cp.async.cg.shared.global [%0], [%1], 16;" :: "r"(s), "l"(g));
}
#define CP_COMMIT() asm volatile("cp.async.commit_group;" ::: "memory")
#define CP_WAIT()   asm volatile("cp.async.wait_group 0;" ::: "memory")

// ---------------- fused precompute ----------------
__global__ void k_pre(const float* __restrict__ node, const float* __restrict__ w_init,
                      const float* __restrict__ b_init, const float* __restrict__ w_t0,
                      const float* __restrict__ b_t0, const float* __restrict__ w_t1,
                      const float* __restrict__ w_fin, const float* __restrict__ b_fin) {
    int i = blockIdx.x, t = threadIdx.x;  // 384 threads
    __shared__ float sn[256], snb[128];
    for (int c = t; c < 256; c += 384) sn[c] = node[i * 256 + c];
    __syncthreads();
    if (t < 128) {
        float acc = b_init[t];
#pragma unroll 8
        for (int k = 0; k < 256; k++) acc += sn[k] * w_init[k * 128 + t];
        snb[t] = acc;
    }
    __syncthreads();
    float a = b_t0[t], b2 = 0.f;
#pragma unroll 8
    for (int k = 0; k < 128; k++) {
        float nv = snb[k];
        a  += nv * w_t0[(128 + k) * 384 + t];
        b2 += nv * w_t0[(256 + k) * 384 + t];
    }
    g_A0[i * 384 + t] = a;
    g_B0h[i * 384 + t] = __float2half_rn(b2);
    if (t < 128) {
        float af = b_fin[t], bf = 0.f;
#pragma unroll 8
        for (int k = 0; k < 128; k++) {
            float nv = snb[k];
            af += nv * w_fin[(128 + k) * 128 + t];
            bf += nv * w_fin[(256 + k) * 128 + t];
        }
        g_Af[i * 128 + t] = af;
        g_Bfh[i * 128 + t] = __float2half_rn(bf);
    }
    for (int x = t; x < 512; x += 384) {
        int idx = i * 512 + x;
        if (idx < 65536) {
            int r = idx >> 9, c = idx & 511;
            g_Wmh[idx] = __float2half_rn(c < 384 ? w_t0[r * 384 + c] : w_fin[r * 128 + (c - 384)]);
        } else if (idx < 65536 + 147456) {
            int j = idx - 65536;
            g_w1rh[j] = __float2half_rn(w_t1[j]);
        } else {
            int j = idx - 212992;
            g_wfrh[j] = __float2half_rn(w_fin[j]);
        }
    }
}

// ---------------- main kernel (R14 structure + A-hoist + Bf SMEM) ----------------
static constexpr int OFF_V  = 0;        // V half 64x392 (50176); E (64x136) aliases head
static constexpr int OFF_U  = 50176;    // U half 64x392 (50176)
static constexpr int OFF_O  = 100352;   // O fp32 64x132 (33792)
static constexpr int OFF_S0 = 134144;   // panel slot 0 (33280)
static constexpr int OFF_S1 = 167424;   // panel slot 1 (33280)
static constexpr int OFF_ST = 200704;   // per-warp staging 8 x (16x20 fp32) (10240)
static constexpr int OFF_BA = 210944;   // A0 row, 384 fp32 (1536)
static constexpr int OFF_BF = 212480;   // Bf tile 64x128 fp16 (16384)
static constexpr int SMEM_BYTES = 228864;

// phase-1 panel: K-chunk c -> rows 32c..+32 of g_Wmh (512 cols), smem stride 520 halves
__device__ __forceinline__ void pf_p1(uint32_t s, int c, int tid) {
    const __half* base = g_Wmh + c * 32 * 512;
    for (int x = tid; x < 2048; x += NTHREADS) {
        int r = x >> 6, c16 = x & 63;
        cpa16(s + r * 1040 + c16 * 16, base + r * 512 + c16 * 8);
    }
}
// W1 panel: K-rows k*32..+32, full 384 cols, smem stride 392 halves
__device__ __forceinline__ void pf_w1(uint32_t s, int k, int tid) {
    const __half* base = g_w1rh + k * 32 * 384;
    for (int x = tid; x < 1536; x += NTHREADS) {
        int r = x / 48, c = x - r * 48;
        cpa16(s + r * 784 + c * 16, base + r * 384 + c * 8);
    }
}
// Wf panel: K-rows h*96..+96 (128 cols), smem stride 136 halves
__device__ __forceinline__ void pf_wf(uint32_t s, int h, int tid) {
    const __half* base = g_wfrh + h * 96 * 128;
    for (int x = tid; x < 1536; x += NTHREADS) {
        int r = x >> 4, c = x & 15;
        cpa16(s + r * 272 + c * 16, base + r * 128 + c * 8);
    }
}
// Bf tile: 64 rows x 128 fp16 = 16 KB linear
__device__ __forceinline__ void pf_bf(uint32_t s, int j0, int tid) {
    const __half* base = g_Bfh + (size_t)j0 * 128;
    for (int x = tid; x < 1024; x += NTHREADS) cpa16(s + x * 16, base + x * 8);
}

typedef wmma::fragment<wmma::matrix_a, 16, 16, 16, __half, wmma::row_major> FragA;
typedef wmma::fragment<wmma::matrix_b, 16, 16, 16, __half, wmma::row_major> FragB;
typedef wmma::fragment<wmma::accumulator, 16, 16, 16, float> FragC;

__global__ __launch_bounds__(NTHREADS, 1)
void k_main(const float* __restrict__ edge, const float* __restrict__ b_t1,
            const float* __restrict__ ln_g, const float* __restrict__ ln_b,
            float* __restrict__ out) {
    extern __shared__ __align__(16) char smem[];
    __half* sE  = (__half*)(smem + OFF_V);     // E stride 136 (dies after phase 1)
    __half* sV  = (__half*)(smem + OFF_V);     // V stride 392 (after phase 1)
    __half* sU  = (__half*)(smem + OFF_U);     // stride 392
    float*  sO  = (float*) (smem + OFF_O);     // stride 132
    float*  sST = (float*) (smem + OFF_ST);
    float*  sBA = (float*) (smem + OFF_BA);
    __half* sBF = (__half*)(smem + OFF_BF);
    const uint32_t sb = smem_u32(smem);
    const uint32_t slotA[2] = { sb + OFF_S0, sb + OFF_S1 };
    __half* const slotP[2] = { (__half*)(smem + OFF_S0), (__half*)(smem + OFF_S1) };

    const int tid = threadIdx.x, lane = tid & 31, wid = tid >> 5;   // 8 warps
    const int i = blockIdx.x >> 3, j0 = (blockIdx.x & 7) * 64;
    float* stg = sST + wid * 320;   // 16x20 fp32 private staging

    pf_p1(slotA[0], 0, tid);
    pf_bf(sb + OFF_BF, j0, tid);
    CP_COMMIT();

    // load E tile -> fp16 (stride 136) + A0 row
    {
        const float4* src = (const float4*)(edge + (size_t)(i * NN + j0) * 128);
        for (int v = tid; v < 64 * 16; v += NTHREADS) {
            int r = v >> 4, c8 = v & 15;
            float4 x0 = src[(size_t)r * 32 + c8 * 2];
            float4 x1 = src[(size_t)r * 32 + c8 * 2 + 1];
            __half2* d = (__half2*)(sE + r * 136 + c8 * 8);
            d[0] = __floats2half2_rn(x0.x, x0.y);
            d[1] = __floats2half2_rn(x0.z, x0.w);
            d[2] = __floats2half2_rn(x1.x, x1.y);
            d[3] = __floats2half2_rn(x1.z, x1.w);
        }
        for (int c = tid; c < 384; c += NTHREADS) sBA[c] = g_A0[i * 384 + c];
    }
    __syncthreads();   // sE ready -> A-frag hoist below is race-free

    // ---- phase 1: [U | O] = E @ [W0e | WfE]; M=64 N=512 K=128, warp tile 64x64 ----
    {
        FragC acc[16];   // [m0..3][n0..3]
#pragma unroll
        for (int q = 0; q < 16; q++) wmma::fill_fragment(acc[q], 0.f);

#pragma unroll 1
        for (int c = 0; c < 4; c++) {
            // hoisted A-frags (k16=0) — overlap LDS latency with cp.async drain + barrier
            FragA af[4];
#pragma unroll
            for (int m = 0; m < 4; m++)
                wmma::load_matrix_sync(af[m], sE + m * 16 * 136 + c * 32, 136);
            CP_WAIT(); __syncthreads();
            if (c < 3) pf_p1(slotA[(c + 1) & 1], c + 1, tid);
            else       pf_w1(slotA[0], 0, tid);
            CP_COMMIT();
            __half* sw = slotP[c & 1];
#pragma unroll
            for (int k16 = 0; k16 < 2; k16++) {
                if (k16 == 1)
#pragma unroll
                    for (int m = 0; m < 4; m++)
                        wmma::load_matrix_sync(af[m], sE + m * 16 * 136 + c * 32 + 16, 136);
#pragma unroll
                for (int n = 0; n < 4; n++) {
                    FragB bf;
                    wmma::load_matrix_sync(bf, sw + k16 * 16 * 520 + wid * 64 + n * 16, 520);
#pragma unroll
                    for (int m = 0; m < 4; m++)
                        wmma::mma_sync(acc[m * 4 + n], af[m], bf, acc[m * 4 + n]);
                }
            }
        }

        // extract: warps 0-5: U cols (bias+relu->fp16 sU); warps 6-7: O cols raw -> sO
        if (wid < 6) {
#pragma unroll
            for (int m = 0; m < 4; m++)
#pragma unroll
                for (int n = 0; n < 4; n++) {
                    wmma::store_matrix_sync(stg, acc[m * 4 + n], 20, wmma::mem_row_major);
                    __syncwarp();
                    int r = m * 16 + (lane >> 1);
                    int cg = wid * 64 + n * 16 + (lane & 1) * 8;
                    const __half2* b0 = (const __half2*)(g_B0h + (size_t)(j0 + r) * 384 + cg);
                    const float* st = stg + (lane >> 1) * 20 + (lane & 1) * 8;
                    __half2* d = (__half2*)(sU + r * 392 + cg);
#pragma unroll
                    for (int q = 0; q < 4; q++) {
                        float2 b0f = __half22float2(b0[q]);
                        float v0 = st[q * 2]     + sBA[cg + q * 2]     + b0f.x;
                        float v1 = st[q * 2 + 1] + sBA[cg + q * 2 + 1] + b0f.y;
                        d[q] = __floats2half2_rn(fmaxf(v0, 0.f), fmaxf(v1, 0.f));
                    }
                    __syncwarp();
                }
        } else {
#pragma unroll
            for (int m = 0; m < 4; m++)
#pragma unroll
                for (int n = 0; n < 4; n++)
                    wmma::store_matrix_sync(sO + m * 16 * 132 + (wid - 6) * 64 + n * 16,
                                            acc[m * 4 + n], 132, wmma::mem_row_major);
        }
    }
    __syncthreads();   // sU complete -> phase-2a A-frag hoist race-free

    // ---- phase 2a: V = relu(U @ W1 + b1); M=64 N=384 K=384, warp tile 64x48 ----
    {
        FragC accV[12];   // [m0..3][n0..2], cols wid*48..
#pragma unroll
        for (int q = 0; q < 12; q++) wmma::fill_fragment(accV[q], 0.f);

#pragma unroll 1
        for (int k = 0; k < 12; k++) {
            FragA af[4];   // hoisted kk=0 A-frags
#pragma unroll
            for (int m = 0; m < 4; m++)
                wmma::load_matrix_sync(af[m], sU + m * 16 * 392 + k * 32, 392);
            CP_WAIT(); __syncthreads();
            int u = 4 + k;
            if (k < 11) pf_w1(slotA[(u + 1) & 1], k + 1, tid);
            else        pf_wf(slotA[0], 0, tid);
            CP_COMMIT();
            __half* sw = slotP[u & 1];
#pragma unroll
            for (int kk = 0; kk < 2; kk++) {
                if (kk == 1)
#pragma unroll
                    for (int m = 0; m < 4; m++)
                        wmma::load_matrix_sync(af[m], sU + m * 16 * 392 + k * 32 + 16, 392);
#pragma unroll
                for (int n = 0; n < 3; n++) {
                    FragB bf;
                    wmma::load_matrix_sync(bf, sw + kk * 16 * 392 + wid * 48 + n * 16, 392);
#pragma unroll
                    for (int m = 0; m < 4; m++)
                        wmma::mma_sync(accV[m * 3 + n], af[m], bf, accV[m * 3 + n]);
                }
            }
        }

        // V extract: bias + relu -> fp16 sV (stride 392), cols wid*48..+48
#pragma unroll
        for (int m = 0; m < 4; m++)
#pragma unroll
            for (int n = 0; n < 3; n++) {
                wmma::store_matrix_sync(stg, accV[m * 3 + n], 20, wmma::mem_row_major);
                __syncwarp();
                int r = m * 16 + (lane >> 1);
                int cl = wid * 48 + n * 16 + (lane & 1) * 8;
                const float* bt = b_t1 + cl;
                const float* st = stg + (lane >> 1) * 20 + (lane & 1) * 8;
                __half2* d = (__half2*)(sV + r * 392 + cl);
#pragma unroll
                for (int q = 0; q < 4; q++) {
                    float v0 = st[q * 2]     + bt[q * 2];
                    float v1 = st[q * 2 + 1] + bt[q * 2 + 1];
                    d[q] = __floats2half2_rn(fmaxf(v0, 0.f), fmaxf(v1, 0.f));
                }
                __syncwarp();
            }
    }
    __syncthreads();   // sV complete -> phase-2b A-frag hoist race-free

    // ---- phase 2b: O += V @ Wf; M=64 N=128 K=384, warp tile 16x64 ----
    {
        const int my = wid & 3, nx = wid >> 2;   // rows my*16, cols nx*64
        FragC accO[4];
#pragma unroll
        for (int n = 0; n < 4; n++)
            wmma::load_matrix_sync(accO[n], sO + my * 16 * 132 + nx * 64 + n * 16, 132,
                                   wmma::mem_row_major);

#pragma unroll 1
        for (int h = 0; h < 4; h++) {
            FragA a;   // hoisted kk=0 A-frag
            wmma::load_matrix_sync(a, sV + my * 16 * 392 + h * 96, 392);
            CP_WAIT(); __syncthreads();
            int u = 16 + h;
            if (h < 3) pf_wf(slotA[(u + 1) & 1], h + 1, tid);
            CP_COMMIT();
            __half* swf = slotP[u & 1];
#pragma unroll
            for (int kk = 0; kk < 6; kk++) {
                if (kk > 0)
                    wmma::load_matrix_sync(a, sV + my * 16 * 392 + h * 96 + kk * 16, 392);
#pragma unroll
                for (int n = 0; n < 4; n++) {
                    FragB b;
                    wmma::load_matrix_sync(b, swf + kk * 16 * 136 + nx * 64 + n * 16, 136);
                    wmma::mma_sync(accO[n], a, b, accO[n]);
                }
            }
        }

        __syncthreads();
#pragma unroll
        for (int n = 0; n < 4; n++)
            wmma::store_matrix_sync(sO + my * 16 * 132 + nx * 64 + n * 16, accO[n], 132,
                                    wmma::mem_row_major);
    }
    __syncthreads();

    // ---- epilogue: O + Af + Bf(SMEM), LayerNorm, store (8 rows per warp) ----
    for (int rr = 0; rr < 8; rr++) {
        int r = wid * 8 + rr;
        float x[4];
        float sum = 0.f;
#pragma unroll
        for (int q = 0; q < 4; q++) {
            int c = lane + q * 32;
            x[q] = sO[r * 132 + c] + g_Af[i * 128 + c] + __half2float(sBF[r * 128 + c]);
            sum += x[q];
        }
#pragma unroll
        for (int off = 16; off; off >>= 1) sum += __shfl_xor_sync(0xffffffffu, sum, off);
        float mu = sum * (1.f / 128.f);
        float vs = 0.f;
#pragma unroll
        for (int q = 0; q < 4; q++) { float d = x[q] - mu; vs += d * d; }
#pragma unroll
        for (int off = 16; off; off >>= 1) vs += __shfl_xor_sync(0xffffffffu, vs, off);
        float inv = rsqrtf(vs * (1.f / 128.f) + 1e-5f);
        size_t base = (size_t)(i * NN + j0 + r) * 128;
#pragma unroll
        for (int q = 0; q < 4; q++) {
            int c = lane + q * 32;
            out[base + c] = (x[q] - mu) * inv * ln_g[c] + ln_b[c];
        }
    }
}

extern "C" void kernel_launch(void* const* d_in, const int* in_sizes, int n_in,
                              void* d_out, int out_size) {
    const float* node   = (const float*)d_in[0];
    const float* edge   = (const float*)d_in[1];
    const float* w_init = (const float*)d_in[2];
    const float* b_init = (const float*)d_in[3];
    const float* w_t0   = (const float*)d_in[4];
    const float* b_t0   = (const float*)d_in[5];
    const float* w_t1   = (const float*)d_in[6];
    const float* b_t1   = (const float*)d_in[7];
    const float* w_fin  = (const float*)d_in[8];
    const float* b_fin  = (const float*)d_in[9];
    const float* ln_g   = (const float*)d_in[10];
    const float* ln_b   = (const float*)d_in[11];
    float* out = (float*)d_out;

    cudaFuncSetAttribute(k_main, cudaFuncAttributeMaxDynamicSharedMemorySize, SMEM_BYTES);

    k_pre<<<NN, 384>>>(node, w_init, b_init, w_t0, b_t0, w_t1, w_fin, b_fin);
    k_main<<<NN * 8, NTHREADS, SMEM_BYTES>>>(edge, b_t1, ln_g, ln_b, out);
}

// round 16
// speedup vs baseline: 1.8070x; 1.8070x over previous
#include <cuda_runtime.h>
#include <cuda_fp16.h>
#include <mma.h>
#include <cstdint>

using namespace nvcuda;

#define NN 512
#define NTHREADS 256

// ---- device scratch ----
__device__ float g_A0[NN * 384];
__device__ __half g_B0h[NN * 384];                  // fp16 per-j trunk bias
__device__ float g_Af[NN * 128];
__device__ __align__(16) __half g_Bfh[NN * 128];    // fp16 per-j final bias (prefetched to SMEM)
__device__ __align__(16) __half g_Wmh[128 * 512];   // merged [w_t0 rows0:128 | w_fin rows0:128]
__device__ __align__(16) __half g_w1rh[384 * 384];  // w_t1 half
__device__ __align__(16) __half g_wfrh[384 * 128];  // w_fin half

__device__ __forceinline__ uint32_t smem_u32(const void* p) {
    uint32_t a;
    asm("{ .reg .u64 t; cvta.to.shared.u64 t, %1; cvt.u32.u64 %0, t; }" : "=r"(a) : "l"(p));
    return a;
}
__device__ __forceinline__ void cpa16(uint32_t s, const void* g) {
    asm volatile("cp.async.cg.shared.global [%0], [%1], 16;" :: "r"(s), "l"(g));
}
#define CP_COMMIT() asm volatile("cp.async.commit_group;" ::: "memory")
#define CP_WAIT()   asm volatile("cp.async.wait_group 0;" ::: "memory")

// ---------------- fused precompute ----------------
__global__ void k_pre(const float* __restrict__ node, const float* __restrict__ w_init,
                      const float* __restrict__ b_init, const float* __restrict__ w_t0,
                      const float* __restrict__ b_t0, const float* __restrict__ w_t1,
                      const float* __restrict__ w_fin, const float* __restrict__ b_fin) {
    int i = blockIdx.x, t = threadIdx.x;  // 384 threads
    __shared__ float sn[256], snb[128];
    for (int c = t; c < 256; c += 384) sn[c] = node[i * 256 + c];
    __syncthreads();
    if (t < 128) {
        float acc = b_init[t];
#pragma unroll 8
        for (int k = 0; k < 256; k++) acc += sn[k] * w_init[k * 128 + t];
        snb[t] = acc;
    }
    __syncthreads();
    float a = b_t0[t], b2 = 0.f;
#pragma unroll 8
    for (int k = 0; k < 128; k++) {
        float nv = snb[k];
        a  += nv * w_t0[(128 + k) * 384 + t];
        b2 += nv * w_t0[(256 + k) * 384 + t];
    }
    g_A0[i * 384 + t] = a;
    g_B0h[i * 384 + t] = __float2half_rn(b2);
    if (t < 128) {
        float af = b_fin[t], bf = 0.f;
#pragma unroll 8
        for (int k = 0; k < 128; k++) {
            float nv = snb[k];
            af += nv * w_fin[(128 + k) * 128 + t];
            bf += nv * w_fin[(256 + k) * 128 + t];
        }
        g_Af[i * 128 + t] = af;
        g_Bfh[i * 128 + t] = __float2half_rn(bf);
    }
    for (int x = t; x < 512; x += 384) {
        int idx = i * 512 + x;
        if (idx < 65536) {
            int r = idx >> 9, c = idx & 511;
            g_Wmh[idx] = __float2half_rn(c < 384 ? w_t0[r * 384 + c] : w_fin[r * 128 + (c - 384)]);
        } else if (idx < 65536 + 147456) {
            int j = idx - 65536;
            g_w1rh[j] = __float2half_rn(w_t1[j]);
        } else {
            int j = idx - 212992;
            g_wfrh[j] = __float2half_rn(w_fin[j]);
        }
    }
}

// ---------------- main kernel (exact R14 structure + Bf SMEM prefetch) ----------------
static constexpr int OFF_V  = 0;        // V half 64x392 (50176); E (64x136) aliases head
static constexpr int OFF_U  = 50176;    // U half 64x392 (50176)
static constexpr int OFF_O  = 100352;   // O fp32 64x132 (33792)
static constexpr int OFF_S0 = 134144;   // panel slot 0 (33280)
static constexpr int OFF_S1 = 167424;   // panel slot 1 (33280)
static constexpr int OFF_ST = 200704;   // per-warp staging 8 x (16x20 fp32) (10240)
static constexpr int OFF_BA = 210944;   // A0 row, 384 fp32 (1536)
static constexpr int OFF_BF = 212480;   // Bf tile 64x128 fp16 (16384)
static constexpr int SMEM_BYTES = 228864;

// phase-1 panel: K-chunk c -> rows 32c..+32 of g_Wmh (512 cols), smem stride 520 halves
__device__ __forceinline__ void pf_p1(uint32_t s, int c, int tid) {
    const __half* base = g_Wmh + c * 32 * 512;
    for (int x = tid; x < 2048; x += NTHREADS) {
        int r = x >> 6, c16 = x & 63;
        cpa16(s + r * 1040 + c16 * 16, base + r * 512 + c16 * 8);
    }
}
// W1 panel: K-rows k*32..+32, full 384 cols, smem stride 392 halves
__device__ __forceinline__ void pf_w1(uint32_t s, int k, int tid) {
    const __half* base = g_w1rh + k * 32 * 384;
    for (int x = tid; x < 1536; x += NTHREADS) {
        int r = x / 48, c = x - r * 48;
        cpa16(s + r * 784 + c * 16, base + r * 384 + c * 8);
    }
}
// Wf panel: K-rows h*96..+96 (128 cols), smem stride 136 halves
__device__ __forceinline__ void pf_wf(uint32_t s, int h, int tid) {
    const __half* base = g_wfrh + h * 96 * 128;
    for (int x = tid; x < 1536; x += NTHREADS) {
        int r = x >> 4, c = x & 15;
        cpa16(s + r * 272 + c * 16, base + r * 128 + c * 8);
    }
}
// Bf tile: 64 rows x 128 fp16 = 16 KB linear
__device__ __forceinline__ void pf_bf(uint32_t s, int j0, int tid) {
    const __half* base = g_Bfh + (size_t)j0 * 128;
    for (int x = tid; x < 1024; x += NTHREADS) cpa16(s + x * 16, base + x * 8);
}

typedef wmma::fragment<wmma::matrix_a, 16, 16, 16, __half, wmma::row_major> FragA;
typedef wmma::fragment<wmma::matrix_b, 16, 16, 16, __half, wmma::row_major> FragB;
typedef wmma::fragment<wmma::accumulator, 16, 16, 16, float> FragC;

__global__ __launch_bounds__(NTHREADS, 1)
void k_main(const float* __restrict__ edge, const float* __restrict__ b_t1,
            const float* __restrict__ ln_g, const float* __restrict__ ln_b,
            float* __restrict__ out) {
    extern __shared__ __align__(16) char smem[];
    __half* sE  = (__half*)(smem + OFF_V);     // E stride 136 (dies after phase 1)
    __half* sV  = (__half*)(smem + OFF_V);     // V stride 392 (after phase 1)
    __half* sU  = (__half*)(smem + OFF_U);     // stride 392
    float*  sO  = (float*) (smem + OFF_O);     // stride 132
    float*  sST = (float*) (smem + OFF_ST);
    float*  sBA = (float*) (smem + OFF_BA);
    __half* sBF = (__half*)(smem + OFF_BF);
    const uint32_t sb = smem_u32(smem);
    const uint32_t slotA[2] = { sb + OFF_S0, sb + OFF_S1 };
    __half* const slotP[2] = { (__half*)(smem + OFF_S0), (__half*)(smem + OFF_S1) };

    const int tid = threadIdx.x, lane = tid & 31, wid = tid >> 5;   // 8 warps
    const int i = blockIdx.x >> 3, j0 = (blockIdx.x & 7) * 64;
    float* stg = sST + wid * 320;   // 16x20 fp32 private staging

    pf_p1(slotA[0], 0, tid);
    pf_bf(sb + OFF_BF, j0, tid);
    CP_COMMIT();

    // load E tile -> fp16 (stride 136) + A0 row
    {
        const float4* src = (const float4*)(edge + (size_t)(i * NN + j0) * 128);
        for (int v = tid; v < 64 * 16; v += NTHREADS) {
            int r = v >> 4, c8 = v & 15;
            float4 x0 = src[(size_t)r * 32 + c8 * 2];
            float4 x1 = src[(size_t)r * 32 + c8 * 2 + 1];
            __half2* d = (__half2*)(sE + r * 136 + c8 * 8);
            d[0] = __floats2half2_rn(x0.x, x0.y);
            d[1] = __floats2half2_rn(x0.z, x0.w);
            d[2] = __floats2half2_rn(x1.x, x1.y);
            d[3] = __floats2half2_rn(x1.z, x1.w);
        }
        for (int c = tid; c < 384; c += NTHREADS) sBA[c] = g_A0[i * 384 + c];
    }

    // ---- phase 1: [U | O] = E @ [W0e | WfE]; M=64 N=512 K=128, warp tile 64x64 ----
    {
        FragC acc[16];   // [m0..3][n0..3]
#pragma unroll
        for (int q = 0; q < 16; q++) wmma::fill_fragment(acc[q], 0.f);

        for (int c = 0; c < 4; c++) {
            CP_WAIT(); __syncthreads();
            if (c < 3) pf_p1(slotA[(c + 1) & 1], c + 1, tid);
            else       pf_w1(slotA[0], 0, tid);          // use idx 4 -> slot 0
            CP_COMMIT();
            __half* sw = slotP[c & 1];
#pragma unroll
            for (int k16 = 0; k16 < 2; k16++) {
                FragA af[4];
#pragma unroll
                for (int m = 0; m < 4; m++)
                    wmma::load_matrix_sync(af[m], sE + m * 16 * 136 + c * 32 + k16 * 16, 136);
#pragma unroll
                for (int n = 0; n < 4; n++) {
                    FragB bf;
                    wmma::load_matrix_sync(bf, sw + k16 * 16 * 520 + wid * 64 + n * 16, 520);
#pragma unroll
                    for (int m = 0; m < 4; m++)
                        wmma::mma_sync(acc[m * 4 + n], af[m], bf, acc[m * 4 + n]);
                }
            }
        }

        // extract: warps 0-5: U cols (bias+relu->fp16 sU); warps 6-7: O cols raw -> sO
        if (wid < 6) {
#pragma unroll
            for (int m = 0; m < 4; m++)
#pragma unroll
                for (int n = 0; n < 4; n++) {
                    wmma::store_matrix_sync(stg, acc[m * 4 + n], 20, wmma::mem_row_major);
                    __syncwarp();
                    int r = m * 16 + (lane >> 1);
                    int cg = wid * 64 + n * 16 + (lane & 1) * 8;
                    const __half2* b0 = (const __half2*)(g_B0h + (size_t)(j0 + r) * 384 + cg);
                    const float* st = stg + (lane >> 1) * 20 + (lane & 1) * 8;
                    __half2* d = (__half2*)(sU + r * 392 + cg);
#pragma unroll
                    for (int q = 0; q < 4; q++) {
                        float2 b0f = __half22float2(b0[q]);
                        float v0 = st[q * 2]     + sBA[cg + q * 2]     + b0f.x;
                        float v1 = st[q * 2 + 1] + sBA[cg + q * 2 + 1] + b0f.y;
                        d[q] = __floats2half2_rn(fmaxf(v0, 0.f), fmaxf(v1, 0.f));
                    }
                    __syncwarp();
                }
        } else {
#pragma unroll
            for (int m = 0; m < 4; m++)
#pragma unroll
                for (int n = 0; n < 4; n++)
                    wmma::store_matrix_sync(sO + m * 16 * 132 + (wid - 6) * 64 + n * 16,
                                            acc[m * 4 + n], 132, wmma::mem_row_major);
        }
    }
    // E dead from here; sU/sO reads ordered by the sync at top of next round.

    // ---- phase 2a: V = relu(U @ W1 + b1); M=64 N=384 K=384, warp tile 64x48 ----
    {
        FragC accV[12];   // [m0..3][n0..2], cols wid*48..
#pragma unroll
        for (int q = 0; q < 12; q++) wmma::fill_fragment(accV[q], 0.f);

        for (int k = 0; k < 12; k++) {
            CP_WAIT(); __syncthreads();
            int u = 4 + k;
            if (k < 11) pf_w1(slotA[(u + 1) & 1], k + 1, tid);
            else        pf_wf(slotA[0], 0, tid);         // use idx 16 -> slot 0
            CP_COMMIT();
            __half* sw = slotP[u & 1];
#pragma unroll
            for (int kk = 0; kk < 2; kk++) {
                FragA af[4];
#pragma unroll
                for (int m = 0; m < 4; m++)
                    wmma::load_matrix_sync(af[m], sU + m * 16 * 392 + k * 32 + kk * 16, 392);
#pragma unroll
                for (int n = 0; n < 3; n++) {
                    FragB bf;
                    wmma::load_matrix_sync(bf, sw + kk * 16 * 392 + wid * 48 + n * 16, 392);
#pragma unroll
                    for (int m = 0; m < 4; m++)
                        wmma::mma_sync(accV[m * 3 + n], af[m], bf, accV[m * 3 + n]);
                }
            }
        }

        // V extract: bias + relu -> fp16 sV (stride 392), cols wid*48..+48
#pragma unroll
        for (int m = 0; m < 4; m++)
#pragma unroll
            for (int n = 0; n < 3; n++) {
                wmma::store_matrix_sync(stg, accV[m * 3 + n], 20, wmma::mem_row_major);
                __syncwarp();
                int r = m * 16 + (lane >> 1);
                int cl = wid * 48 + n * 16 + (lane & 1) * 8;
                const float* bt = b_t1 + cl;
                const float* st = stg + (lane >> 1) * 20 + (lane & 1) * 8;
                __half2* d = (__half2*)(sV + r * 392 + cl);
#pragma unroll
                for (int q = 0; q < 4; q++) {
                    float v0 = st[q * 2]     + bt[q * 2];
                    float v1 = st[q * 2 + 1] + bt[q * 2 + 1];
                    d[q] = __floats2half2_rn(fmaxf(v0, 0.f), fmaxf(v1, 0.f));
                }
                __syncwarp();
            }
    }

    // ---- phase 2b: O += V @ Wf; M=64 N=128 K=384, warp tile 16x64 ----
    {
        const int my = wid & 3, nx = wid >> 2;   // rows my*16, cols nx*64
        FragC accO[4];
#pragma unroll
        for (int n = 0; n < 4; n++)
            wmma::load_matrix_sync(accO[n], sO + my * 16 * 132 + nx * 64 + n * 16, 132,
                                   wmma::mem_row_major);

        for (int h = 0; h < 4; h++) {
            CP_WAIT(); __syncthreads();          // also orders sV writes before reads (h=0)
            int u = 16 + h;
            if (h < 3) pf_wf(slotA[(u + 1) & 1], h + 1, tid);
            CP_COMMIT();
            __half* swf = slotP[u & 1];
#pragma unroll
            for (int kk = 0; kk < 6; kk++) {
                FragA a;
                wmma::load_matrix_sync(a, sV + my * 16 * 392 + h * 96 + kk * 16, 392);
#pragma unroll
                for (int n = 0; n < 4; n++) {
                    FragB b;
                    wmma::load_matrix_sync(b, swf + kk * 16 * 136 + nx * 64 + n * 16, 136);
                    wmma::mma_sync(accO[n], a, b, accO[n]);
                }
            }
        }

        __syncthreads();
#pragma unroll
        for (int n = 0; n < 4; n++)
            wmma::store_matrix_sync(sO + my * 16 * 132 + nx * 64 + n * 16, accO[n], 132,
                                    wmma::mem_row_major);
    }
    __syncthreads();

    // ---- epilogue: O + Af + Bf(SMEM), LayerNorm, store (8 rows per warp) ----
    for (int rr = 0; rr < 8; rr++) {
        int r = wid * 8 + rr;
        float x[4];
        float sum = 0.f;
#pragma unroll
        for (int q = 0; q < 4; q++) {
            int c = lane + q * 32;
            x[q] = sO[r * 132 + c] + g_Af[i * 128 + c] + __half2float(sBF[r * 128 + c]);
            sum += x[q];
        }
#pragma unroll
        for (int off = 16; off; off >>= 1) sum += __shfl_xor_sync(0xffffffffu, sum, off);
        float mu = sum * (1.f / 128.f);
        float vs = 0.f;
#pragma unroll
        for (int q = 0; q < 4; q++) { float d = x[q] - mu; vs += d * d; }
#pragma unroll
        for (int off = 16; off; off >>= 1) vs += __shfl_xor_sync(0xffffffffu, vs, off);
        float inv = rsqrtf(vs * (1.f / 128.f) + 1e-5f);
        size_t base = (size_t)(i * NN + j0 + r) * 128;
#pragma unroll
        for (int q = 0; q < 4; q++) {
            int c = lane + q * 32;
            out[base + c] = (x[q] - mu) * inv * ln_g[c] + ln_b[c];
        }
    }
}

extern "C" void kernel_launch(void* const* d_in, const int* in_sizes, int n_in,
                              void* d_out, int out_size) {
    const float* node   = (const float*)d_in[0];
    const float* edge   = (const float*)d_in[1];
    const float* w_init = (const float*)d_in[2];
    const float* b_init = (const float*)d_in[3];
    const float* w_t0   = (const float*)d_in[4];
    const float* b_t0   = (const float*)d_in[5];
    const float* w_t1   = (const float*)d_in[6];
    const float* b_t1   = (const float*)d_in[7];
    const float* w_fin  = (const float*)d_in[8];
    const float* b_fin  = (const float*)d_in[9];
    const float* ln_g   = (const float*)d_in[10];
    const float* ln_b   = (const float*)d_in[11];
    float* out = (float*)d_out;

    cudaFuncSetAttribute(k_main, cudaFuncAttributeMaxDynamicSharedMemorySize, SMEM_BYTES);

    k_pre<<<NN, 384>>>(node, w_init, b_init, w_t0, b_t0, w_t1, w_fin, b_fin);
    k_main<<<NN * 8, NTHREADS, SMEM_BYTES>>>(edge, b_t1, ln_g, ln_b, out);
}